// round 2
// baseline (speedup 1.0000x reference)
#include <cuda_runtime.h>
#include <cstdint>

#define BATCH    4096
#define FNUM     1024
#define RCNT     19
#define RDIM     1024

#define TPB      (RCNT * 32)      // 608 threads: warp w handles relation r=w
#define ROW      (FNUM * RCNT)    // 19456 floats per batch row
#define ROW4     (ROW / 4)        // 4864 float4 per row (608 * 8)
#define SMEM_B   (ROW * 4)        // 77824 bytes

// Precomputed W[f*19 + r] = sum_e U[f,e] * R[r,e]
__device__ float g_W[FNUM * RCNT];

// ---------------------------------------------------------------------------
// Kernel A: W = U @ R^T   (1024 x 19) — tiny, ~3 us
// grid = FNUM blocks, 256 threads; thread owns 4 consecutive e (one float4)
// ---------------------------------------------------------------------------
__global__ void compute_w_kernel(const float* __restrict__ U,
                                 const float* __restrict__ R) {
    const int f   = blockIdx.x;
    const int tid = threadIdx.x;          // 0..255
    const float4 u = reinterpret_cast<const float4*>(U + (size_t)f * RDIM)[tid];

    float acc[RCNT];
#pragma unroll
    for (int r = 0; r < RCNT; ++r) {
        const float4 rv = reinterpret_cast<const float4*>(R + (size_t)r * RDIM)[tid];
        acc[r] = u.x * rv.x + u.y * rv.y + u.z * rv.z + u.w * rv.w;
    }

    // warp tree reduce each of the 19 partials
#pragma unroll
    for (int r = 0; r < RCNT; ++r) {
        float v = acc[r];
#pragma unroll
        for (int off = 16; off > 0; off >>= 1)
            v += __shfl_down_sync(0xffffffffu, v, off);
        acc[r] = v;
    }

    __shared__ float s_part[RCNT][8];
    const int warp = tid >> 5, lane = tid & 31;
    if (lane == 0) {
#pragma unroll
        for (int r = 0; r < RCNT; ++r) s_part[r][warp] = acc[r];
    }
    __syncthreads();
    if (tid < RCNT) {
        float s = 0.f;
#pragma unroll
        for (int w = 0; w < 8; ++w) s += s_part[tid][w];
        g_W[f * RCNT + tid] = s;
    }
}

// ---------------------------------------------------------------------------
// Kernel B: scores[b,r] = sum_f conv[b,f,r] * W[f,r]
// Persistent blocks, 608 threads (19 warps == 19 relations).
// Row staged through SMEM via cp.async (coalesced float4), then read at
// stride 19 (conflict-free: gcd(19,32)=1). W held in 32 registers/thread,
// loaded once per persistent block. Reduction = one warp shuffle tree.
// ---------------------------------------------------------------------------
__global__ void __launch_bounds__(TPB, 2)
score_kernel(const float* __restrict__ conv, float* __restrict__ out) {
    extern __shared__ float s_row[];      // ROW floats
    const int tid  = threadIdx.x;
    const int lane = tid & 31;
    const int r    = tid >> 5;            // warp id == relation id (0..18)

    // Load this thread's 32 W values once (reused for every batch row)
    float w[32];
#pragma unroll
    for (int k = 0; k < 32; ++k)
        w[k] = g_W[(lane + 32 * k) * RCNT + r];

    const unsigned s_base =
        (unsigned)__cvta_generic_to_shared(s_row);

    for (int b = blockIdx.x; b < BATCH; b += gridDim.x) {
        const float4* src =
            reinterpret_cast<const float4*>(conv + (size_t)b * ROW);

        // Coalesced bulk copy: 8 x 16B per thread, bypassing registers
#pragma unroll
        for (int j = 0; j < 8; ++j) {
            const int idx = tid + TPB * j;            // 0..4863
            const unsigned saddr = s_base + idx * 16u;
            asm volatile("cp.async.cg.shared.global [%0], [%1], 16;\n"
                         :: "r"(saddr), "l"(src + idx));
        }
        asm volatile("cp.async.commit_group;\n");
        asm volatile("cp.async.wait_group 0;\n");
        __syncthreads();

        // Strided SMEM reads: addr = (lane+32k)*19 + r  -> conflict-free
        float acc = 0.f;
#pragma unroll
        for (int k = 0; k < 32; ++k)
            acc = fmaf(s_row[(lane + 32 * k) * RCNT + r], w[k], acc);

        // warp == relation: intra-warp reduce only
#pragma unroll
        for (int off = 16; off > 0; off >>= 1)
            acc += __shfl_down_sync(0xffffffffu, acc, off);

        if (lane == 0) out[(size_t)b * RCNT + r] = acc;
        __syncthreads();   // protect s_row before next iteration's copy
    }
}

// ---------------------------------------------------------------------------
extern "C" void kernel_launch(void* const* d_in, const int* in_sizes, int n_in,
                              void* d_out, int out_size) {
    // Identify inputs by element count (robust to ordering)
    const float* conv = nullptr;
    const float* Rm   = nullptr;
    const float* Um   = nullptr;
    for (int i = 0; i < n_in; ++i) {
        if (in_sizes[i] == BATCH * FNUM * RCNT)      conv = (const float*)d_in[i];
        else if (in_sizes[i] == RCNT * RDIM)         Rm   = (const float*)d_in[i];
        else if (in_sizes[i] == FNUM * RDIM)         Um   = (const float*)d_in[i];
    }
    float* out = (float*)d_out;

    // Opt in to >48KB dynamic smem (idempotent, capture-safe host call)
    static int attr_done = 0;
    if (!attr_done) {
        cudaFuncSetAttribute(score_kernel,
                             cudaFuncAttributeMaxDynamicSharedMemorySize, SMEM_B);
        attr_done = 1;
    }

    int dev = 0, nsm = 148;
    cudaGetDevice(&dev);
    cudaDeviceGetAttribute(&nsm, cudaDevAttrMultiProcessorCount, dev);

    compute_w_kernel<<<FNUM, 256>>>(Um, Rm);
    score_kernel<<<2 * nsm, TPB, SMEM_B>>>(conv, out);
}